// round 17
// baseline (speedup 1.0000x reference)
#include <cuda_runtime.h>
#include <cuda_fp16.h>
#include <cstdint>
#include <cstddef>

// ----------------------------------------------------------------------------
// B=2, T=2048, C=1024, H=16, hs=64 ; M = B*T = 4096
// Two independent per-batch chains (rows 0-2047 / 2048-4095) on two streams.
// ----------------------------------------------------------------------------
#define MROWS 4096
#define CDIM  1024
#define FDIM  4096
#define TLEN  2048
#define NHEAD 16
#define HS    64
#define MHALF (MROWS / 2)

__device__ __half g_h1[MROWS * CDIM];
__device__ __half g_q [MROWS * CDIM];          // [B,H,T,hs]
__device__ __half g_kk[MROWS * CDIM];
__device__ __half g_v [MROWS * CDIM];          // [B,H,T,hs] row-major
__device__ __half g_attn[MROWS * CDIM];
__device__ float  g_x1[MROWS * CDIM];          // fp32 residual path
__device__ __half g_h2[MROWS * CDIM];
__device__ __half g_ff1[(size_t)MROWS * FDIM];
__device__ __half g_wqT[CDIM * CDIM];          // Bt[n][k]
__device__ __half g_wkT[CDIM * CDIM];
__device__ __half g_wvT[CDIM * CDIM];
__device__ __half g_wpT[CDIM * CDIM];
__device__ __half g_wf1T[(size_t)CDIM * FDIM];
__device__ __half g_wf2T[(size_t)CDIM * FDIM];

// ----------------------------------------------------------------------------
// Helpers
// ----------------------------------------------------------------------------
__device__ __forceinline__ uint32_t smem_u32(const void* p) {
    return (uint32_t)__cvta_generic_to_shared(p);
}
__device__ __forceinline__ void cp16(uint32_t dst, const void* src) {
    asm volatile("cp.async.cg.shared.global [%0], [%1], 16;\n" :: "r"(dst), "l"(src));
}
__device__ __forceinline__ void cp_commit() {
    asm volatile("cp.async.commit_group;\n" ::: "memory");
}
__device__ __forceinline__ void cp_wait1() {
    asm volatile("cp.async.wait_group 1;\n" ::: "memory");
}
__device__ __forceinline__ void mma16(float* d, const uint32_t* a, const uint32_t* b) {
    asm volatile(
        "mma.sync.aligned.m16n8k16.row.col.f32.f16.f16.f32 "
        "{%0,%1,%2,%3},{%4,%5,%6,%7},{%8,%9},{%0,%1,%2,%3};"
        : "+f"(d[0]), "+f"(d[1]), "+f"(d[2]), "+f"(d[3])
        : "r"(a[0]), "r"(a[1]), "r"(a[2]), "r"(a[3]), "r"(b[0]), "r"(b[1]));
}
__device__ __forceinline__ void ldsm_x4(uint32_t* r, uint32_t addr) {
    asm volatile("ldmatrix.sync.aligned.m8n8.x4.shared.b16 {%0,%1,%2,%3}, [%4];"
                 : "=r"(r[0]), "=r"(r[1]), "=r"(r[2]), "=r"(r[3]) : "r"(addr));
}
__device__ __forceinline__ void ldsm_x4t(uint32_t* r, uint32_t addr) {
    asm volatile("ldmatrix.sync.aligned.m8n8.x4.trans.shared.b16 {%0,%1,%2,%3}, [%4];"
                 : "=r"(r[0]), "=r"(r[1]), "=r"(r[2]), "=r"(r[3]) : "r"(addr));
}

// ----------------------------------------------------------------------------
// LayerNorm: warp-per-row (8 rows/block); mbase = first row of this chain
// ----------------------------------------------------------------------------
__global__ void __launch_bounds__(256) ln_k(int mode, int mbase,
                                            const float* __restrict__ x_ext,
                                            const float* __restrict__ g,
                                            const float* __restrict__ b)
{
    const float* in = (mode == 0) ? x_ext : g_x1;
    __half* out     = (mode == 0) ? g_h1  : g_h2;
    const int lane = threadIdx.x & 31;
    const int row = mbase + blockIdx.x * 8 + (threadIdx.x >> 5);
    const size_t base = (size_t)row * CDIM;

    float4 v[8];
    float s = 0.f, s2 = 0.f;
#pragma unroll
    for (int i = 0; i < 8; i++) {
        v[i] = *(const float4*)(in + base + lane * 4 + i * 128);
        s  += v[i].x + v[i].y + v[i].z + v[i].w;
        s2 += v[i].x * v[i].x + v[i].y * v[i].y + v[i].z * v[i].z + v[i].w * v[i].w;
    }
#pragma unroll
    for (int off = 16; off; off >>= 1) {
        s  += __shfl_xor_sync(0xffffffffu, s,  off);
        s2 += __shfl_xor_sync(0xffffffffu, s2, off);
    }
    const float mu = s * (1.f / CDIM);
    const float rstd = rsqrtf(s2 * (1.f / CDIM) - mu * mu + 1e-5f);
#pragma unroll
    for (int i = 0; i < 8; i++) {
        int c = lane * 4 + i * 128;
        float4 gg = *(const float4*)(g + c);
        float4 bb = *(const float4*)(b + c);
        *(__half2*)(out + base + c) =
            __floats2half2_rn((v[i].x - mu) * rstd * gg.x + bb.x,
                              (v[i].y - mu) * rstd * gg.y + bb.y);
        *(__half2*)(out + base + c + 2) =
            __floats2half2_rn((v[i].z - mu) * rstd * gg.z + bb.z,
                              (v[i].w - mu) * rstd * gg.w + bb.w);
    }
}

// ----------------------------------------------------------------------------
// Weight convert+transpose (fp32 [r][c] -> fp16 [c][r]), 32x32 tiles.
// ----------------------------------------------------------------------------
__device__ __forceinline__ void tr_tile(const float* __restrict__ ip,
                                        __half* __restrict__ op,
                                        int R, int Cc, int c0, int r0)
{
    __shared__ float t[32][33];
    int tx = threadIdx.x & 31, ty = threadIdx.x >> 5;
#pragma unroll
    for (int i = 0; i < 32; i += 8)
        t[ty + i][tx] = ip[(size_t)(r0 + ty + i) * Cc + c0 + tx];
    __syncthreads();
#pragma unroll
    for (int i = 0; i < 32; i += 8)
        op[(size_t)(c0 + ty + i) * R + r0 + tx] = __float2half(t[tx][ty + i]);
}

__global__ void __launch_bounds__(256) conv_qkv(const float* __restrict__ Wq,
                                                const float* __restrict__ Wk,
                                                const float* __restrict__ Wv)
{
    int m = blockIdx.z >> 4, batch = blockIdx.z & 15;
    const float* src = (m == 0) ? Wq : ((m == 1) ? Wk : Wv);
    __half* dst = (m == 0) ? g_wqT : ((m == 1) ? g_wkT : g_wvT);
    tr_tile(src + (size_t)batch * CDIM * HS, dst + (size_t)batch * CDIM * HS,
            CDIM, HS, blockIdx.x * 32, blockIdx.y * 32);
}

__global__ void __launch_bounds__(256) conv_wp(const float* __restrict__ Wp)
{
    tr_tile(Wp, g_wpT, CDIM, CDIM, blockIdx.x * 32, blockIdx.y * 32);
}

__global__ void __launch_bounds__(256) conv_ff(const float* __restrict__ W1,
                                               const float* __restrict__ W2)
{
    int id = blockIdx.x * 32 + blockIdx.y;
    if (blockIdx.z == 0) {
        int c_t = id & 127, r_t = id >> 7;
        tr_tile(W1, g_wf1T, CDIM, FDIM, c_t * 32, r_t * 32);
    } else {
        int c_t = id & 31, r_t = id >> 5;
        tr_tile(W2, g_wf2T, FDIM, CDIM, c_t * 32, r_t * 32);
    }
}

// ----------------------------------------------------------------------------
// fp16 mma.sync GEMM, CTA tile 128x128, 8 warps, warp 64x32; 2 CTAs/SM.
// mbase = row offset of this chain's half.
// ----------------------------------------------------------------------------
#define GPITCH 72
#define STG_HALVES ((128 + 128) * GPITCH)
#define MG_SMEM    (3 * STG_HALVES * 2)     // 110592 B

template <int MODE>
__global__ void __launch_bounds__(256, 2) mgemm(int mbase,
                                                const float* __restrict__ bias,
                                                const float* __restrict__ resid,
                                                float* __restrict__ outp)
{
    constexpr int K = (MODE == 3) ? 4096 : 1024;
    constexpr int NKIT = K / 64;

    extern __shared__ __half smh[];
    const int tid = threadIdx.x, lane = tid & 31, wid = tid >> 5;
    const int wm = wid & 1, wn = wid >> 1;
    const int m0 = mbase + blockIdx.y * 128;
    const int n0 = blockIdx.x * 128;

    const __half* A;
    if      (MODE == 0) A = g_h1;
    else if (MODE == 1) A = g_attn;
    else if (MODE == 2) A = g_h2;
    else                A = g_ff1;

    const __half* B;
    if (MODE == 0) B = (blockIdx.z == 0) ? g_wqT : ((blockIdx.z == 1) ? g_wkT : g_wvT);
    else if (MODE == 1) B = g_wpT;
    else if (MODE == 2) B = g_wf1T;
    else                B = g_wf2T;

    float acc[4][4][4] = {};

    auto load_stage = [&](int j, int s) {
        __half* As = smh + s * STG_HALVES;
        __half* Bs = As + 128 * GPITCH;
#pragma unroll
        for (int i = 0; i < 4; i++) {
            int c = tid + i * 256;
            int row = c >> 3, kc = c & 7;
            cp16(smem_u32(As + row * GPITCH + kc * 8),
                 A + (size_t)(m0 + row) * K + j * 64 + kc * 8);
        }
#pragma unroll
        for (int i = 0; i < 4; i++) {
            int c = tid + i * 256;
            int row = c >> 3, kc = c & 7;
            cp16(smem_u32(Bs + row * GPITCH + kc * 8),
                 B + (size_t)(n0 + row) * K + j * 64 + kc * 8);
        }
        cp_commit();
    };

    const int arow = (lane & 7) + ((lane >> 3) & 1) * 8;
    const int ahalf = (lane >> 4) & 1;
    uint32_t offA[4], offB[2];
#pragma unroll
    for (int mi = 0; mi < 4; mi++)
        offA[mi] = ((wm * 64 + mi * 16 + arow) * GPITCH + ahalf * 8) * 2;
#pragma unroll
    for (int g = 0; g < 2; g++)
        offB[g] = ((wn * 32 + g * 16 + arow) * GPITCH + ahalf * 8) * 2;

    load_stage(0, 0);
    load_stage(1, 1);

    for (int it = 0; it < NKIT; it++) {
        int s = it % 3;
        cp_wait1();
        __syncthreads();
        if (it + 2 < NKIT) load_stage(it + 2, (it + 2) % 3);
        else cp_commit();

        uint32_t AsU = smem_u32(smh + s * STG_HALVES);
        uint32_t BsU = AsU + 128 * GPITCH * 2;

#pragma unroll
        for (int ks = 0; ks < 4; ks++) {
            uint32_t af[4][4], bb[2][4];
#pragma unroll
            for (int mi = 0; mi < 4; mi++) ldsm_x4(af[mi], AsU + offA[mi] + ks * 32);
#pragma unroll
            for (int g = 0; g < 2; g++)  ldsm_x4(bb[g], BsU + offB[g] + ks * 32);
#pragma unroll
            for (int mi = 0; mi < 4; mi++)
#pragma unroll
                for (int g = 0; g < 2; g++) {
                    uint32_t blo[2] = {bb[g][0], bb[g][2]};
                    uint32_t bhi[2] = {bb[g][1], bb[g][3]};
                    mma16(acc[mi][g * 2],     af[mi], blo);
                    mma16(acc[mi][g * 2 + 1], af[mi], bhi);
                }
        }
    }

#pragma unroll
    for (int mi = 0; mi < 4; mi++) {
#pragma unroll
        for (int nj = 0; nj < 4; nj++) {
#pragma unroll
            for (int half = 0; half < 2; half++) {
                int gm = m0 + wm * 64 + mi * 16 + (lane >> 2) + half * 8;
                int gn = n0 + wn * 32 + nj * 8 + (lane & 3) * 2;
                float v0 = acc[mi][nj][half * 2 + 0];
                float v1 = acc[mi][nj][half * 2 + 1];
                if (MODE == 0) {
                    int bb2 = gm >> 11, t = gm & 2047;
                    int h = gn >> 6, d0 = gn & 63;
                    __half* sel = (blockIdx.z == 0) ? g_q : ((blockIdx.z == 1) ? g_kk : g_v);
                    __half* op = sel + ((size_t)((bb2 * 16 + h) * 2048 + t)) * 64 + d0;
                    *(__half2*)op = __floats2half2_rn(v0, v1);
                } else if (MODE == 1) {
                    size_t o = (size_t)gm * 1024 + gn;
                    g_x1[o]     = v0 + bias[gn]     + resid[o];
                    g_x1[o + 1] = v1 + bias[gn + 1] + resid[o + 1];
                } else if (MODE == 2) {
                    size_t o = (size_t)gm * 4096 + gn;
                    *(__half2*)(g_ff1 + o) =
                        __floats2half2_rn(fmaxf(v0 + bias[gn], 0.f),
                                          fmaxf(v1 + bias[gn + 1], 0.f));
                } else {
                    size_t o = (size_t)gm * 1024 + gn;
                    outp[o]     = v0 + bias[gn]     + g_x1[o];
                    outp[o + 1] = v1 + bias[gn + 1] + g_x1[o + 1];
                }
            }
        }
    }
}

// ----------------------------------------------------------------------------
// fp16 tensor-core causal flash attention; bhbase selects this chain's batch.
// ----------------------------------------------------------------------------
#define QPITCH 72
#define KPITCH 72
#define VPITCH 72
#define PPITCH 40
#define AT_KOFF (128 * QPITCH)
#define AT_VOFF (AT_KOFF + 2 * 32 * KPITCH)
#define AT_POFF (AT_VOFF + 2 * 32 * VPITCH)
#define AT_SMEM ((AT_POFF + 4 * 32 * PPITCH) * 2)  // 47104 B

__global__ void __launch_bounds__(128) attn_k(int bhbase)
{
    extern __shared__ __half smA[];
    const int tid = threadIdx.x, lane = tid & 31, wid = tid >> 5;
    const int bh = bhbase + blockIdx.y;
    const int rb = (int)gridDim.x - 1 - (int)blockIdx.x;
    const int R0 = rb * 128;
    const size_t qkbase = (size_t)bh * TLEN * HS;

    uint32_t QsU = smem_u32(smA);
    uint32_t KsU[2], VtU[2];
    KsU[0] = QsU + AT_KOFF * 2;  KsU[1] = KsU[0] + 32 * KPITCH * 2;
    VtU[0] = QsU + AT_VOFF * 2;  VtU[1] = VtU[0] + 32 * VPITCH * 2;
    uint32_t PsU = QsU + (AT_POFF + wid * 32 * PPITCH) * 2;

    {
        const __half* src = g_q + qkbase + (size_t)R0 * 64;
#pragma unroll
        for (int i = 0; i < 8; i++) {
            int c = tid + i * 128;
            int row = c >> 3, ch = c & 7;
            cp16(QsU + (row * QPITCH + ch * 8) * 2, src + row * 64 + ch * 8);
        }
    }
    auto load_tile = [&](int kt, int b) {
        const __half* ks = g_kk + qkbase + (size_t)kt * 32 * 64;
        const __half* vs = g_v  + qkbase + (size_t)kt * 32 * 64;
#pragma unroll
        for (int i = 0; i < 2; i++) {
            int c = tid + i * 128;
            int row = c >> 3, ch = c & 7;
            cp16(KsU[b] + (row * KPITCH + ch * 8) * 2, ks + row * 64 + ch * 8);
            cp16(VtU[b] + (row * VPITCH + ch * 8) * 2, vs + row * 64 + ch * 8);
        }
    };

    const int NT = R0 / 32 + 4;
    const int maskstart = R0 / 32;

    load_tile(0, 0);
    cp_commit();

    const int arow = (lane & 7) + ((lane >> 3) & 1) * 8;
    const int ahalf = (lane >> 4) & 1;
    uint32_t offQ[2], offP[2], offK[2], offV[4];
#pragma unroll
    for (int mi = 0; mi < 2; mi++) {
        offQ[mi] = ((wid * 32 + mi * 16 + arow) * QPITCH + ahalf * 8) * 2;
        offP[mi] = ((mi * 16 + arow) * PPITCH + ahalf * 8) * 2;
    }
#pragma unroll
    for (int g = 0; g < 2; g++) offK[g] = ((g * 16 + arow) * KPITCH + ahalf * 8) * 2;
    const int vk = (lane & 7) + ((lane >> 4) & 1) * 8;
    const int vn = ((lane >> 3) & 1) * 8;
#pragma unroll
    for (int g = 0; g < 4; g++) offV[g] = (vk * VPITCH + g * 16 + vn) * 2;

    uint32_t qf[2][4][4];
    float oacc[2][8][4] = {};
    float m_run[4] = {-1e30f, -1e30f, -1e30f, -1e30f};
    float l_run[4] = {};

    const int srow = lane >> 2;
    const int scol = (lane & 3) * 2;

    for (int it = 0; it < NT; it++) {
        __syncthreads();
        if (it + 1 < NT) load_tile(it + 1, (it + 1) & 1);
        cp_commit();
        cp_wait1();
        __syncthreads();

        if (it == 0) {
            const __half2 sc = __float2half2_rn(0.125f);
#pragma unroll
            for (int mi = 0; mi < 2; mi++)
#pragma unroll
                for (int kt = 0; kt < 4; kt++) {
                    ldsm_x4(qf[mi][kt], QsU + offQ[mi] + kt * 32);
#pragma unroll
                    for (int i = 0; i < 4; i++) {
                        __half2 h = *(__half2*)&qf[mi][kt][i];
                        h = __hmul2(h, sc);
                        qf[mi][kt][i] = *(uint32_t*)&h;
                    }
                }
        }

        const uint32_t Kb = KsU[it & 1], Vb = VtU[it & 1];

        float sacc[2][4][4] = {};
#pragma unroll
        for (int kt = 0; kt < 4; kt++) {
#pragma unroll
            for (int g = 0; g < 2; g++) {
                uint32_t kb[4];
                ldsm_x4(kb, Kb + offK[g] + kt * 32);
                uint32_t blo[2] = {kb[0], kb[2]}, bhi[2] = {kb[1], kb[3]};
#pragma unroll
                for (int mi = 0; mi < 2; mi++) {
                    mma16(sacc[mi][g * 2],     qf[mi][kt], blo);
                    mma16(sacc[mi][g * 2 + 1], qf[mi][kt], bhi);
                }
            }
        }

        if (it >= maskstart) {
            const int colbase = it * 32 + scol;
#pragma unroll
            for (int mi = 0; mi < 2; mi++) {
                const int rowb = R0 + wid * 32 + mi * 16 + srow;
#pragma unroll
                for (int nt = 0; nt < 4; nt++)
#pragma unroll
                    for (int j = 0; j < 4; j++) {
                        int col = colbase + nt * 8 + (j & 1);
                        int row = rowb + 8 * (j >> 1);
                        if (col > row) sacc[mi][nt][j] = -1e30f;
                    }
            }
        }

#pragma unroll
        for (int mi = 0; mi < 2; mi++) {
#pragma unroll
            for (int hf = 0; hf < 2; hf++) {
                const int slot = mi * 2 + hf;
                float vmax = m_run[slot];
#pragma unroll
                for (int nt = 0; nt < 4; nt++) {
                    vmax = fmaxf(vmax, sacc[mi][nt][hf * 2]);
                    vmax = fmaxf(vmax, sacc[mi][nt][hf * 2 + 1]);
                }
                vmax = fmaxf(vmax, __shfl_xor_sync(0xffffffffu, vmax, 1));
                vmax = fmaxf(vmax, __shfl_xor_sync(0xffffffffu, vmax, 2));
                const float mnew = vmax;
                const float scale = __expf(m_run[slot] - mnew);
                float lsum = 0.f;
                const int prow = mi * 16 + srow + 8 * hf;
#pragma unroll
                for (int nt = 0; nt < 4; nt++) {
                    float p0 = __expf(sacc[mi][nt][hf * 2]     - mnew);
                    float p1 = __expf(sacc[mi][nt][hf * 2 + 1] - mnew);
                    lsum += p0 + p1;
                    __half2 ph = __floats2half2_rn(p0, p1);
                    asm volatile("st.shared.u32 [%0], %1;"
                                 :: "r"(PsU + (prow * PPITCH + nt * 8 + scol) * 2),
                                    "r"(*(uint32_t*)&ph) : "memory");
                }
                lsum += __shfl_xor_sync(0xffffffffu, lsum, 1);
                lsum += __shfl_xor_sync(0xffffffffu, lsum, 2);
                l_run[slot] = l_run[slot] * scale + lsum;
                m_run[slot] = mnew;
#pragma unroll
                for (int nt = 0; nt < 8; nt++) {
                    oacc[mi][nt][hf * 2]     *= scale;
                    oacc[mi][nt][hf * 2 + 1] *= scale;
                }
            }
        }

#pragma unroll
        for (int kt = 0; kt < 2; kt++) {
            uint32_t pa[2][4];
#pragma unroll
            for (int mi = 0; mi < 2; mi++) ldsm_x4(pa[mi], PsU + offP[mi] + kt * 32);
#pragma unroll
            for (int g = 0; g < 4; g++) {
                uint32_t vb[4];
                ldsm_x4t(vb, Vb + offV[g] + kt * 16 * VPITCH * 2);
                uint32_t blo[2] = {vb[0], vb[2]}, bhi[2] = {vb[1], vb[3]};
#pragma unroll
                for (int mi = 0; mi < 2; mi++) {
                    mma16(oacc[mi][g * 2],     pa[mi], blo);
                    mma16(oacc[mi][g * 2 + 1], pa[mi], bhi);
                }
            }
        }
    }

    const int b = bh >> 4, h = bh & 15;
#pragma unroll
    for (int mi = 0; mi < 2; mi++) {
#pragma unroll
        for (int hf = 0; hf < 2; hf++) {
            const float inv = 1.f / l_run[mi * 2 + hf];
            const int grow = R0 + wid * 32 + mi * 16 + srow + 8 * hf;
            __half* op = g_attn + ((size_t)(b * 2048 + grow)) * 1024 + h * 64 + scol;
#pragma unroll
            for (int nt = 0; nt < 8; nt++)
                *(__half2*)(op + nt * 8) =
                    __floats2half2_rn(oacc[mi][nt][hf * 2] * inv,
                                      oacc[mi][nt][hf * 2 + 1] * inv);
        }
    }
}

// ----------------------------------------------------------------------------
// Launch: two independent per-batch chains (stream 0 = batch 0, sB = batch 1),
// weight converts on sW. Each chain's kernel tails are backfilled by the other.
// ----------------------------------------------------------------------------
extern "C" void kernel_launch(void* const* d_in, const int* in_sizes, int n_in,
                              void* d_out, int out_size)
{
    const float* x     = (const float*)d_in[0];
    const float* Wq    = (const float*)d_in[1];
    const float* Wk    = (const float*)d_in[2];
    const float* Wv    = (const float*)d_in[3];
    const float* Wproj = (const float*)d_in[4];
    const float* bproj = (const float*)d_in[5];
    const float* g1    = (const float*)d_in[6];
    const float* b1    = (const float*)d_in[7];
    const float* g2    = (const float*)d_in[8];
    const float* b2    = (const float*)d_in[9];
    const float* Wff1  = (const float*)d_in[10];
    const float* bff1  = (const float*)d_in[11];
    const float* Wff2  = (const float*)d_in[12];
    const float* bff2  = (const float*)d_in[13];
    float* out = (float*)d_out;

    static cudaStream_t sW = nullptr, sB = nullptr;
    static cudaEvent_t efork = nullptr, e_qkv = nullptr, e_all = nullptr, eB = nullptr;
    if (sW == nullptr) {
        cudaStreamCreateWithFlags(&sW, cudaStreamNonBlocking);
        cudaStreamCreateWithFlags(&sB, cudaStreamNonBlocking);
        cudaEventCreateWithFlags(&efork, cudaEventDisableTiming);
        cudaEventCreateWithFlags(&e_qkv, cudaEventDisableTiming);
        cudaEventCreateWithFlags(&e_all, cudaEventDisableTiming);
        cudaEventCreateWithFlags(&eB,    cudaEventDisableTiming);
        cudaFuncSetAttribute(mgemm<0>, cudaFuncAttributeMaxDynamicSharedMemorySize, MG_SMEM);
        cudaFuncSetAttribute(mgemm<1>, cudaFuncAttributeMaxDynamicSharedMemorySize, MG_SMEM);
        cudaFuncSetAttribute(mgemm<2>, cudaFuncAttributeMaxDynamicSharedMemorySize, MG_SMEM);
        cudaFuncSetAttribute(mgemm<3>, cudaFuncAttributeMaxDynamicSharedMemorySize, MG_SMEM);
        cudaFuncSetAttribute(attn_k,   cudaFuncAttributeMaxDynamicSharedMemorySize, AT_SMEM);
    }

    // fork both auxiliary streams from stream 0
    cudaEventRecord(efork, 0);
    cudaStreamWaitEvent(sW, efork, 0);
    cudaStreamWaitEvent(sB, efork, 0);

    // weight converts (sW)
    conv_qkv<<<dim3(2, 32, 48), 256, 0, sW>>>(Wq, Wk, Wv);
    cudaEventRecord(e_qkv, sW);
    conv_wp <<<dim3(32, 32),     256, 0, sW>>>(Wproj);
    conv_ff <<<dim3(128, 32, 2), 256, 0, sW>>>(Wff1, Wff2);
    cudaEventRecord(e_all, sW);

    const dim3 ggrid(CDIM / 128, MHALF / 128);
    const dim3 ggrid3(CDIM / 128, MHALF / 128, 3);
    const dim3 fgrid(FDIM / 128, MHALF / 128);
    const dim3 agrid(TLEN / 128, NHEAD);

    // ---- chain A: batch 0 (rows 0..2047) on stream 0 ----
    ln_k<<<MHALF / 8, 256>>>(0, 0, x, g1, b1);
    cudaStreamWaitEvent(0, e_qkv, 0);
    mgemm<0><<<ggrid3, 256, MG_SMEM>>>(0, nullptr, nullptr, nullptr);
    attn_k<<<agrid, 128, AT_SMEM>>>(0);
    cudaStreamWaitEvent(0, e_all, 0);
    mgemm<1><<<ggrid, 256, MG_SMEM>>>(0, bproj, x, nullptr);
    ln_k<<<MHALF / 8, 256>>>(1, 0, nullptr, g2, b2);
    mgemm<2><<<fgrid, 256, MG_SMEM>>>(0, bff1, nullptr, nullptr);
    mgemm<3><<<ggrid, 256, MG_SMEM>>>(0, bff2, nullptr, out);

    // ---- chain B: batch 1 (rows 2048..4095) on sB ----
    ln_k<<<MHALF / 8, 256, 0, sB>>>(0, MHALF, x, g1, b1);
    cudaStreamWaitEvent(sB, e_qkv, 0);
    mgemm<0><<<ggrid3, 256, MG_SMEM, sB>>>(MHALF, nullptr, nullptr, nullptr);
    attn_k<<<agrid, 128, AT_SMEM, sB>>>(NHEAD);
    cudaStreamWaitEvent(sB, e_all, 0);
    mgemm<1><<<ggrid, 256, MG_SMEM, sB>>>(MHALF, bproj, x, nullptr);
    ln_k<<<MHALF / 8, 256, 0, sB>>>(1, MHALF, nullptr, g2, b2);
    mgemm<2><<<fgrid, 256, MG_SMEM, sB>>>(MHALF, bff1, nullptr, nullptr);
    mgemm<3><<<ggrid, 256, MG_SMEM, sB>>>(MHALF, bff2, nullptr, out);
    cudaEventRecord(eB, sB);

    // join chain B back into stream 0 (required for capture; makes completion
    // depend on both chains)
    cudaStreamWaitEvent(0, eB, 0);
}